// round 1
// baseline (speedup 1.0000x reference)
#include <cuda_runtime.h>
#include <math.h>

#define BB   16
#define CC   256
#define HWp  4096
#define NTOT (16*256*4096)

// ---------------- device-global scratch (no allocations allowed) ----------------
__device__ float g_spatial[BB*CC];
__device__ float g_mod[BB*CC];
__device__ float g_y1[NTOT];
__device__ float g_sc[NTOT];
__device__ float g_bb[NTOT];
__device__ float g_scale1[CC], g_bias1[CC];
__device__ float g_scaleS[CC], g_biasS[CC];
__device__ float g_scale2[CC], g_bias2[CC];

__device__ __forceinline__ float silu_f(float z) {
    return z / (1.0f + expf(-z));
}

// ---------------------------------------------------------------------------
// Kernel 1: spatial_proj[b,c] = mean over HxW of depthwise 3x3 SAME conv.
// Uses inclusion-exclusion: only plane sum, boundary row/col sums, corners.
// grid = B*C blocks of 256 threads.
// ---------------------------------------------------------------------------
__global__ void k_spatial(const float* __restrict__ x, const float* __restrict__ w_ch) {
    int bc = blockIdx.x;
    const float* p = x + (size_t)bc * HWp;
    float T = 0.f, R0 = 0.f, R1 = 0.f, C0 = 0.f, C1 = 0.f;
    for (int k = threadIdx.x; k < HWp; k += 256) {
        float v = p[k];
        int i = k >> 6, j = k & 63;
        T += v;
        R0 += (i == 0)  ? v : 0.f;
        R1 += (i == 63) ? v : 0.f;
        C0 += (j == 0)  ? v : 0.f;
        C1 += (j == 63) ? v : 0.f;
    }
    __shared__ float sm[5][8];
    float vals[5] = {T, R0, R1, C0, C1};
    int lane = threadIdx.x & 31, w = threadIdx.x >> 5;
#pragma unroll
    for (int i = 0; i < 5; i++) {
        float v = vals[i];
#pragma unroll
        for (int o = 16; o; o >>= 1) v += __shfl_down_sync(0xffffffffu, v, o);
        if (lane == 0) sm[i][w] = v;
    }
    __syncthreads();
    if (threadIdx.x == 0) {
        float r[5];
#pragma unroll
        for (int i = 0; i < 5; i++) {
            float s = 0.f;
#pragma unroll
            for (int j = 0; j < 8; j++) s += sm[i][j];
            r[i] = s;
        }
        float Tt = r[0], Ra = r[1], Rb = r[2], Ca = r[3], Cb = r[4];
        float x00 = p[0], x0W = p[63], xH0 = p[63 * 64], xHW = p[4095];
        // S[ky][kx]: sum of x over the valid shifted window for tap (ky,kx)
        float S[9] = {
            Tt - Rb - Cb + xHW,  Tt - Rb,  Tt - Rb - Ca + xH0,
            Tt - Cb,             Tt,       Tt - Ca,
            Tt - Ra - Cb + x0W,  Tt - Ra,  Tt - Ra - Ca + x00
        };
        int c = bc & 255;
        const float* wc = w_ch + c * 9;
        float s = 0.f;
#pragma unroll
        for (int k = 0; k < 9; k++) s += wc[k] * S[k];
        g_spatial[bc] = s * (1.0f / 4096.0f);
    }
}

// ---------------------------------------------------------------------------
// Kernel 2: gating MLP -> g_mod[b,c]. grid = B blocks of 256 threads.
// ---------------------------------------------------------------------------
__global__ void k_gate(const float* __restrict__ dce,
                       const float* __restrict__ w_dce, const float* __restrict__ b_dce,
                       const float* __restrict__ w_sh,  const float* __restrict__ b_sh,
                       const float* __restrict__ w_ex,  const float* __restrict__ b_ex) {
    int b = blockIdx.x, t = threadIdx.x;
    __shared__ float pooled[128], ms[256], hs[128];
    if (t < 128) {
        const float* dp = dce + b * 100 * 128 + t;
        float s = 0.f;
        for (int l = 0; l < 100; l++) s += dp[l * 128];
        pooled[t] = s * (1.0f / 100.0f);
    }
    __syncthreads();
    {
        const float* wr = w_dce + t * 128;
        float s = b_dce[t];
#pragma unroll 8
        for (int k = 0; k < 128; k++) s += pooled[k] * wr[k];
        ms[t] = s * g_spatial[b * 256 + t];
    }
    __syncthreads();
    if (t < 128) {
        const float* wr = w_sh + t * 256;
        float s = b_sh[t];
#pragma unroll 8
        for (int k = 0; k < 256; k++) s += ms[k] * wr[k];
        hs[t] = fmaxf(s, 0.f);
    }
    __syncthreads();
    {
        const float* wr = w_ex + t * 128;
        float s = b_ex[t];
#pragma unroll 8
        for (int k = 0; k < 128; k++) s += hs[k] * wr[k];
        g_mod[b * 256 + t] = 1.0f / (1.0f + expf(-s));
    }
}

// ---------------------------------------------------------------------------
// Kernel 3: conv1 3x3 SAME, 256->256, input xm = x * mod (computed on the fly).
// CTA tile: 32x32 spatial x 16 output channels for one batch.
// Thread micro-tile: 8 co x (2x4) px -> 64 accumulators.
// grid = (4 spatial tiles, 16 co groups, 16 batch), 256 threads.
// ---------------------------------------------------------------------------
__global__ __launch_bounds__(256, 2) void k_conv1(const float* __restrict__ x,
                                                  const float* __restrict__ w1) {
    __shared__ float tile[34][35];   // input halo tile, pad to 35 for <=2-way conflicts
    __shared__ float wsm[16][9];

    int b   = blockIdx.z;
    int cog = blockIdx.y;                    // co base = cog*16
    int tr0 = (blockIdx.x >> 1) * 32;
    int tc0 = (blockIdx.x & 1) * 32;
    int tid = threadIdx.x;
    int co_sub = tid >> 7;                   // 0/1 -> 8-co half
    int ptid   = tid & 127;
    int lr = (ptid >> 3) * 2;                // 0..30 step 2
    int lc = (ptid & 7) * 4;                 // 0..28 step 4

    float acc[8][2][4];
#pragma unroll
    for (int o = 0; o < 8; o++)
#pragma unroll
        for (int pr = 0; pr < 2; pr++)
#pragma unroll
            for (int pc = 0; pc < 4; pc++) acc[o][pr][pc] = 0.f;

    for (int ci = 0; ci < 256; ci++) {
        __syncthreads();
        float modv = g_mod[b * 256 + ci];
        const float* xp = x + ((size_t)(b * 256 + ci)) * HWp;
#pragma unroll
        for (int it = 0; it < 5; it++) {
            int idx = tid + it * 256;
            if (idx < 34 * 34) {
                int r = idx / 34, cc = idx - r * 34;
                int gr = tr0 - 1 + r, gc = tc0 - 1 + cc;
                float v = 0.f;
                if ((unsigned)gr < 64u && (unsigned)gc < 64u) v = xp[gr * 64 + gc] * modv;
                tile[r][cc] = v;
            }
        }
        if (tid < 144) {
            int o = tid / 9, k = tid - o * 9;
            wsm[o][k] = w1[((size_t)(cog * 16 + o) * 256 + ci) * 9 + k];
        }
        __syncthreads();

        float xin[4][6];
#pragma unroll
        for (int r = 0; r < 4; r++)
#pragma unroll
            for (int c2 = 0; c2 < 6; c2++) xin[r][c2] = tile[lr + r][lc + c2];

#pragma unroll
        for (int o = 0; o < 8; o++) {
            float wv[9];
#pragma unroll
            for (int k = 0; k < 9; k++) wv[k] = wsm[co_sub * 8 + o][k];
#pragma unroll
            for (int pr = 0; pr < 2; pr++)
#pragma unroll
                for (int pc = 0; pc < 4; pc++) {
                    float s = acc[o][pr][pc];
#pragma unroll
                    for (int ky = 0; ky < 3; ky++)
#pragma unroll
                        for (int kx = 0; kx < 3; kx++)
                            s += wv[ky * 3 + kx] * xin[pr + ky][pc + kx];
                    acc[o][pr][pc] = s;
                }
        }
    }

#pragma unroll
    for (int o = 0; o < 8; o++) {
        int co = cog * 16 + co_sub * 8 + o;
#pragma unroll
        for (int pr = 0; pr < 2; pr++) {
            float4 v = make_float4(acc[o][pr][0], acc[o][pr][1], acc[o][pr][2], acc[o][pr][3]);
            *(float4*)&g_y1[((size_t)(b * 256 + co)) * HWp + (tr0 + lr + pr) * 64 + tc0 + lc] = v;
        }
    }
}

// ---------------------------------------------------------------------------
// Kernel 4: 1x1 conv as per-batch SGEMM, C_out x HW = W(256x256) @ in(256xHW).
// MODE 0: in = x * mod        -> out = g_sc   (shortcut conv)
// MODE 1: in = silu(bn1(y1))  -> out = g_bb   (conv2)
// Tile 64co x 64px, K-chunks of 16; 4x4 micro-tile; float4 smem IO.
// grid = (64 px tiles, 4 co tiles, 16 batch), 256 threads.
// ---------------------------------------------------------------------------
template <int MODE>
__global__ __launch_bounds__(256) void k_gemm1x1(const float* __restrict__ xin,
                                                 const float* __restrict__ w) {
    __shared__ float Asm[16][68];
    __shared__ float Bsm[16][68];
    int b   = blockIdx.z;
    int cob = blockIdx.y * 64;
    int pxb = blockIdx.x * 64;
    int tid = threadIdx.x;
    const float* in = (MODE == 0) ? xin : g_y1;
    float* out      = (MODE == 0) ? g_sc : g_bb;

    float acc[4][4];
#pragma unroll
    for (int i = 0; i < 4; i++)
#pragma unroll
        for (int j = 0; j < 4; j++) acc[i][j] = 0.f;

    int trow = tid >> 4;   // co quad (16)
    int tcol = tid & 15;   // px quad (16)

    for (int kb = 0; kb < 256; kb += 16) {
        __syncthreads();
        {   // weights: Asm[k][co]
            int col = tid & 63, kq = tid >> 6;
            float4 wv = *(const float4*)&w[(size_t)(cob + col) * 256 + kb + kq * 4];
            Asm[kq * 4 + 0][col] = wv.x;
            Asm[kq * 4 + 1][col] = wv.y;
            Asm[kq * 4 + 2][col] = wv.z;
            Asm[kq * 4 + 3][col] = wv.w;
        }
        {   // activations: Bsm[k][px] with fused pre-op
            int k = tid >> 4, p4 = (tid & 15) * 4;
            int ch = kb + k;
            float4 v = *(const float4*)&in[((size_t)(b * 256 + ch)) * HWp + pxb + p4];
            if (MODE == 0) {
                float mm = g_mod[b * 256 + ch];
                v.x *= mm; v.y *= mm; v.z *= mm; v.w *= mm;
            } else {
                float s = g_scale1[ch], t = g_bias1[ch];
                v.x = silu_f(fmaf(s, v.x, t));
                v.y = silu_f(fmaf(s, v.y, t));
                v.z = silu_f(fmaf(s, v.z, t));
                v.w = silu_f(fmaf(s, v.w, t));
            }
            *(float4*)&Bsm[k][p4] = v;
        }
        __syncthreads();
#pragma unroll
        for (int k = 0; k < 16; k++) {
            float4 a  = *(const float4*)&Asm[k][trow * 4];
            float4 bv = *(const float4*)&Bsm[k][tcol * 4];
            acc[0][0] += a.x * bv.x; acc[0][1] += a.x * bv.y; acc[0][2] += a.x * bv.z; acc[0][3] += a.x * bv.w;
            acc[1][0] += a.y * bv.x; acc[1][1] += a.y * bv.y; acc[1][2] += a.y * bv.z; acc[1][3] += a.y * bv.w;
            acc[2][0] += a.z * bv.x; acc[2][1] += a.z * bv.y; acc[2][2] += a.z * bv.z; acc[2][3] += a.z * bv.w;
            acc[3][0] += a.w * bv.x; acc[3][1] += a.w * bv.y; acc[3][2] += a.w * bv.z; acc[3][3] += a.w * bv.w;
        }
    }
#pragma unroll
    for (int i = 0; i < 4; i++) {
        float4 v = make_float4(acc[i][0], acc[i][1], acc[i][2], acc[i][3]);
        *(float4*)&out[((size_t)(b * 256 + cob + trow * 4 + i)) * HWp + pxb + tcol * 4] = v;
    }
}

// ---------------------------------------------------------------------------
// Kernel 5: per-channel BN stats (training mode, biased var) -> scale/bias.
// mode 0: y1 -> (scale1,bias1); 1: sc -> (scaleS,biasS); 2: bb -> (scale2,bias2)
// grid = 256 channels, 256 threads.
// ---------------------------------------------------------------------------
__global__ void k_stats(int mode, const float* __restrict__ g, const float* __restrict__ be) {
    const float* buf = (mode == 0) ? g_y1 : ((mode == 1) ? g_sc : g_bb);
    int c = blockIdx.x;
    float s = 0.f, s2 = 0.f;
    for (int b = 0; b < 16; b++) {
        const float4* p = (const float4*)(buf + ((size_t)(b * 256 + c)) * HWp);
        for (int i = threadIdx.x; i < 1024; i += 256) {
            float4 v = p[i];
            s  += v.x + v.y + v.z + v.w;
            s2 += v.x * v.x + v.y * v.y + v.z * v.z + v.w * v.w;
        }
    }
    int lane = threadIdx.x & 31, w = threadIdx.x >> 5;
#pragma unroll
    for (int o = 16; o; o >>= 1) {
        s  += __shfl_down_sync(0xffffffffu, s, o);
        s2 += __shfl_down_sync(0xffffffffu, s2, o);
    }
    __shared__ float sm[2][8];
    if (lane == 0) { sm[0][w] = s; sm[1][w] = s2; }
    __syncthreads();
    if (threadIdx.x == 0) {
        float S = 0.f, S2 = 0.f;
#pragma unroll
        for (int j = 0; j < 8; j++) { S += sm[0][j]; S2 += sm[1][j]; }
        const float inv_n = 1.0f / (16.0f * 4096.0f);
        float mean = S * inv_n;
        float var  = S2 * inv_n - mean * mean;
        float sc = g[c] * rsqrtf(var + 1e-5f);
        float bi = be[c] - mean * sc;
        if (mode == 0)      { g_scale1[c] = sc; g_bias1[c] = bi; }
        else if (mode == 1) { g_scaleS[c] = sc; g_biasS[c] = bi; }
        else                { g_scale2[c] = sc; g_bias2[c] = bi; }
    }
}

// ---------------------------------------------------------------------------
// Kernel 6: out = silu( bn2(bb) + bns(sc) ), elementwise float4.
// ---------------------------------------------------------------------------
__global__ void k_final(float* __restrict__ out) {
    int i4 = blockIdx.x * 256 + threadIdx.x;
    if (i4 >= NTOT / 4) return;
    int idx = i4 * 4;
    int c = (idx >> 12) & 255;
    float s2 = g_scale2[c], b2 = g_bias2[c];
    float ss = g_scaleS[c], bs = g_biasS[c];
    float4 vb = ((const float4*)g_bb)[i4];
    float4 vs = ((const float4*)g_sc)[i4];
    float4 r;
    r.x = silu_f(fmaf(s2, vb.x, b2) + fmaf(ss, vs.x, bs));
    r.y = silu_f(fmaf(s2, vb.y, b2) + fmaf(ss, vs.y, bs));
    r.z = silu_f(fmaf(s2, vb.z, b2) + fmaf(ss, vs.z, bs));
    r.w = silu_f(fmaf(s2, vb.w, b2) + fmaf(ss, vs.w, bs));
    ((float4*)out)[i4] = r;
}

// ---------------------------------------------------------------------------
extern "C" void kernel_launch(void* const* d_in, const int* in_sizes, int n_in,
                              void* d_out, int out_size) {
    const float* x     = (const float*)d_in[0];
    const float* dce   = (const float*)d_in[1];
    const float* w_dce = (const float*)d_in[2];
    const float* b_dce = (const float*)d_in[3];
    const float* w_ch  = (const float*)d_in[4];
    const float* w_sh  = (const float*)d_in[5];
    const float* b_sh  = (const float*)d_in[6];
    const float* w_ex  = (const float*)d_in[7];
    const float* b_ex  = (const float*)d_in[8];
    const float* w1    = (const float*)d_in[9];
    const float* g1    = (const float*)d_in[10];
    const float* be1   = (const float*)d_in[11];
    const float* w2    = (const float*)d_in[12];
    const float* g2    = (const float*)d_in[13];
    const float* be2   = (const float*)d_in[14];
    const float* wsc   = (const float*)d_in[15];
    const float* gs    = (const float*)d_in[16];
    const float* bes   = (const float*)d_in[17];

    k_spatial<<<4096, 256>>>(x, w_ch);
    k_gate<<<16, 256>>>(dce, w_dce, b_dce, w_sh, b_sh, w_ex, b_ex);
    k_conv1<<<dim3(4, 16, 16), 256>>>(x, w1);
    k_gemm1x1<0><<<dim3(64, 4, 16), 256>>>(x, wsc);       // shortcut 1x1 on xm
    k_stats<<<256, 256>>>(0, g1, be1);                    // bn1 params from y1
    k_stats<<<256, 256>>>(1, gs, bes);                    // bns params from sc
    k_gemm1x1<1><<<dim3(64, 4, 16), 256>>>(nullptr, w2);  // conv2 on silu(bn1(y1))
    k_stats<<<256, 256>>>(2, g2, be2);                    // bn2 params from bb
    k_final<<<16384, 256>>>((float*)d_out);
}